// round 1
// baseline (speedup 1.0000x reference)
#include <cuda_runtime.h>
#include <mma.h>
#include <math.h>

using namespace nvcuda;

#define BATCH 4
#define SEQ   4096
#define DIMC  1024
#define NHEAD 16
#define HDIM  64
#define NWIN  16
#define BLKT  256            // tokens per window block
#define MTOK  (BATCH*SEQ)    // 16384 rows
#define QCH   64             // q rows handled per CTA
#define ATTN_SCALE 0.125f    // 64^-0.5

// scratch: q, k, v, attn_out  (4 x 16384 x 1024 floats = 256 MB)
__device__ float g_scratch[4ull * MTOK * DIMC];

// ---------------------------------------------------------------------------
// C[M,N] = A[M,K] @ Bw[N,K]^T + bias[N]   (M=16384 or arbitrary mult of 128,
// N=K=1024), tf32 wmma, 128x128 CTA tile, BK=16, 8 warps (4x2).
// ---------------------------------------------------------------------------
__global__ __launch_bounds__(256) void gemm_tf32_bias(
    const float* __restrict__ A, const float* __restrict__ Bw,
    const float* __restrict__ bias, float* __restrict__ C)
{
    const int K = DIMC, N = DIMC;
    __shared__ float As[128][16];
    __shared__ float Bs[128][16];
    __shared__ float stage[8][16][16];

    const int tid  = threadIdx.x;
    const int warp = tid >> 5;
    const int lane = tid & 31;
    const int wm = warp & 3;      // 4 warps along M (32 rows each)
    const int wn = warp >> 2;     // 2 warps along N (64 cols each)
    const int rowBase = blockIdx.y * 128;
    const int colBase = blockIdx.x * 128;

    wmma::fragment<wmma::accumulator,16,16,8,float> acc[2][4];
    #pragma unroll
    for (int i = 0; i < 2; i++)
        #pragma unroll
        for (int j = 0; j < 4; j++)
            wmma::fill_fragment(acc[i][j], 0.0f);

    for (int k0 = 0; k0 < K; k0 += 16) {
        #pragma unroll
        for (int t = 0; t < 2; t++) {
            int lin = tid + t * 256;          // 0..511 -> 512 float4 per tile
            int r = lin >> 2;
            int c = (lin & 3) * 4;
            *(float4*)&As[r][c] = *(const float4*)&A [(size_t)(rowBase + r) * K + k0 + c];
            *(float4*)&Bs[r][c] = *(const float4*)&Bw[(size_t)(colBase + r) * K + k0 + c];
        }
        __syncthreads();

        #pragma unroll
        for (int kk = 0; kk < 16; kk += 8) {
            wmma::fragment<wmma::matrix_a,16,16,8,wmma::precision::tf32,wmma::row_major> af[2];
            wmma::fragment<wmma::matrix_b,16,16,8,wmma::precision::tf32,wmma::col_major> bf[4];
            #pragma unroll
            for (int i = 0; i < 2; i++) {
                wmma::load_matrix_sync(af[i], &As[wm*32 + i*16][kk], 16);
                #pragma unroll
                for (int e = 0; e < af[i].num_elements; e++)
                    af[i].x[e] = wmma::__float_to_tf32(af[i].x[e]);
            }
            #pragma unroll
            for (int j = 0; j < 4; j++) {
                wmma::load_matrix_sync(bf[j], &Bs[wn*64 + j*16][kk], 16);
                #pragma unroll
                for (int e = 0; e < bf[j].num_elements; e++)
                    bf[j].x[e] = wmma::__float_to_tf32(bf[j].x[e]);
            }
            #pragma unroll
            for (int i = 0; i < 2; i++)
                #pragma unroll
                for (int j = 0; j < 4; j++)
                    wmma::mma_sync(acc[i][j], af[i], bf[j], acc[i][j]);
        }
        __syncthreads();
    }

    // epilogue: add bias, write fp32
    #pragma unroll
    for (int i = 0; i < 2; i++) {
        #pragma unroll
        for (int j = 0; j < 4; j++) {
            wmma::store_matrix_sync(&stage[warp][0][0], acc[i][j], 16, wmma::mem_row_major);
            __syncwarp();
            int r0 = rowBase + wm*32 + i*16;
            int c0 = colBase + wn*64 + j*16;
            int r  = lane >> 1;
            int cc = (lane & 1) * 8;
            float4 v0, v1;
            v0.x = stage[warp][r][cc+0] + bias[c0+cc+0];
            v0.y = stage[warp][r][cc+1] + bias[c0+cc+1];
            v0.z = stage[warp][r][cc+2] + bias[c0+cc+2];
            v0.w = stage[warp][r][cc+3] + bias[c0+cc+3];
            v1.x = stage[warp][r][cc+4] + bias[c0+cc+4];
            v1.y = stage[warp][r][cc+5] + bias[c0+cc+5];
            v1.z = stage[warp][r][cc+6] + bias[c0+cc+6];
            v1.w = stage[warp][r][cc+7] + bias[c0+cc+7];
            *(float4*)&C[(size_t)(r0 + r) * N + c0 + cc]     = v0;
            *(float4*)&C[(size_t)(r0 + r) * N + c0 + cc + 4] = v1;
            __syncwarp();
        }
    }
}

// ---------------------------------------------------------------------------
// Block-local attention. One CTA per (b,h,w, qchunk of 64 rows).
//   S = Qc(64x64) @ K^T(64x256) * scale -> softmax -> attn write
//   O = P(64x256) @ V(256x64) -> attn_out scratch ([B,N,DIM] layout)
// ---------------------------------------------------------------------------
#define SLD 260   // padded leading dim for the 64x256 score tile

__global__ __launch_bounds__(256) void attn_kernel(
    const float* __restrict__ q, const float* __restrict__ k,
    const float* __restrict__ v, float* __restrict__ o,
    float* __restrict__ attnp)
{
    extern __shared__ float sm[];
    float* Ks = sm;                  // 256*64
    float* Vs = Ks + 256*64;         // 256*64
    float* Qs = Vs + 256*64;         // 64*64
    float* Ss = Qs + 64*64;          // 64*SLD

    const int tid  = threadIdx.x;
    const int warp = tid >> 5;
    const int wm = warp & 3;         // 4 warps along q-rows (16 each)
    const int wn = warp >> 2;        // 2 warps along cols

    const int bhw = blockIdx.x;      // b*256 + h*16 + w
    const int qc  = blockIdx.y;      // 0..3
    const int w = bhw & 15;
    const int h = (bhw >> 4) & 15;
    const int b = bhw >> 8;

    const size_t tokBase = (size_t)b * SEQ + (size_t)w * BLKT;
    const int    colBase = h * HDIM;

    const float* Kg = k + tokBase * DIMC + colBase;
    const float* Vg = v + tokBase * DIMC + colBase;
    const float* Qg = q + (tokBase + (size_t)qc * QCH) * DIMC + colBase;

    // load K,V (256x64) and Q chunk (64x64), all float4
    for (int t = tid; t < 256*16; t += 256) {
        int r = t >> 4, c4 = t & 15;
        ((float4*)Ks)[t] = ((const float4*)(Kg + (size_t)r * DIMC))[c4];
        ((float4*)Vs)[t] = ((const float4*)(Vg + (size_t)r * DIMC))[c4];
    }
    for (int t = tid; t < 64*16; t += 256) {
        int r = t >> 4, c4 = t & 15;
        ((float4*)Qs)[t] = ((const float4*)(Qg + (size_t)r * DIMC))[c4];
    }
    __syncthreads();

    // ---- S = Q @ K^T : each warp 16 rows x 128 cols (8 n-frags) ----
    {
        wmma::fragment<wmma::accumulator,16,16,8,float> sacc[8];
        #pragma unroll
        for (int j = 0; j < 8; j++) wmma::fill_fragment(sacc[j], 0.0f);
        #pragma unroll
        for (int d0 = 0; d0 < HDIM; d0 += 8) {
            wmma::fragment<wmma::matrix_a,16,16,8,wmma::precision::tf32,wmma::row_major> af;
            wmma::load_matrix_sync(af, Qs + (wm*16) * HDIM + d0, HDIM);
            #pragma unroll
            for (int e = 0; e < af.num_elements; e++)
                af.x[e] = wmma::__float_to_tf32(af.x[e]);
            #pragma unroll
            for (int j = 0; j < 8; j++) {
                wmma::fragment<wmma::matrix_b,16,16,8,wmma::precision::tf32,wmma::col_major> bf;
                wmma::load_matrix_sync(bf, Ks + (size_t)(wn*128 + j*16) * HDIM + d0, HDIM);
                #pragma unroll
                for (int e = 0; e < bf.num_elements; e++)
                    bf.x[e] = wmma::__float_to_tf32(bf.x[e]);
                wmma::mma_sync(sacc[j], af, bf, sacc[j]);
            }
        }
        #pragma unroll
        for (int j = 0; j < 8; j++)
            wmma::store_matrix_sync(Ss + (wm*16)*SLD + wn*128 + j*16, sacc[j],
                                    SLD, wmma::mem_row_major);
    }
    __syncthreads();

    // ---- softmax: 4 threads per row, strided columns (conflict-free) ----
    {
        const int row  = tid >> 2;
        const int part = tid & 3;
        float* srow = Ss + row * SLD;
        float mx = -1e30f;
        #pragma unroll
        for (int j = 0; j < 64; j++) mx = fmaxf(mx, srow[j*4 + part]);
        mx = fmaxf(mx, __shfl_xor_sync(0xffffffffu, mx, 1));
        mx = fmaxf(mx, __shfl_xor_sync(0xffffffffu, mx, 2));
        float sum = 0.0f;
        #pragma unroll
        for (int j = 0; j < 64; j++) {
            float e = __expf((srow[j*4 + part] - mx) * ATTN_SCALE);
            srow[j*4 + part] = e;
            sum += e;
        }
        sum += __shfl_xor_sync(0xffffffffu, sum, 1);
        sum += __shfl_xor_sync(0xffffffffu, sum, 2);
        const float inv = 1.0f / sum;
        if (attnp) {
            float* arow = attnp + ((((size_t)b*NHEAD + h)*NWIN + w)*BLKT
                                   + qc*QCH + row) * BLKT;
            #pragma unroll
            for (int j = 0; j < 64; j++) {
                float p = srow[j*4 + part] * inv;
                srow[j*4 + part] = p;
                arow[j*4 + part] = p;
            }
        } else {
            #pragma unroll
            for (int j = 0; j < 64; j++)
                srow[j*4 + part] *= inv;
        }
    }
    __syncthreads();

    // ---- O = P @ V : each warp 16 rows x 32 cols (2 n-frags) ----
    {
        wmma::fragment<wmma::accumulator,16,16,8,float> oacc[2];
        wmma::fill_fragment(oacc[0], 0.0f);
        wmma::fill_fragment(oacc[1], 0.0f);
        #pragma unroll 4
        for (int k0 = 0; k0 < BLKT; k0 += 8) {
            wmma::fragment<wmma::matrix_a,16,16,8,wmma::precision::tf32,wmma::row_major> af;
            wmma::load_matrix_sync(af, Ss + (wm*16)*SLD + k0, SLD);
            #pragma unroll
            for (int e = 0; e < af.num_elements; e++)
                af.x[e] = wmma::__float_to_tf32(af.x[e]);
            #pragma unroll
            for (int fn = 0; fn < 2; fn++) {
                wmma::fragment<wmma::matrix_b,16,16,8,wmma::precision::tf32,wmma::row_major> bf;
                wmma::load_matrix_sync(bf, Vs + (size_t)k0 * HDIM + wn*32 + fn*16, HDIM);
                #pragma unroll
                for (int e = 0; e < bf.num_elements; e++)
                    bf.x[e] = wmma::__float_to_tf32(bf.x[e]);
                wmma::mma_sync(oacc[fn], af, bf, oacc[fn]);
            }
        }
        #pragma unroll
        for (int fn = 0; fn < 2; fn++) {
            float* optr = o + (tokBase + (size_t)qc*QCH + wm*16) * DIMC
                            + colBase + wn*32 + fn*16;
            wmma::store_matrix_sync(optr, oacc[fn], DIMC, wmma::mem_row_major);
        }
    }
}

// ---------------------------------------------------------------------------
extern "C" void kernel_launch(void* const* d_in, const int* in_sizes, int n_in,
                              void* d_out, int out_size)
{
    const float* x  = (const float*)d_in[0];
    const float* Wq = (const float*)d_in[1];
    const float* bq = (const float*)d_in[2];
    const float* Wk = (const float*)d_in[3];
    const float* bk = (const float*)d_in[4];
    const float* Wv = (const float*)d_in[5];
    const float* bv = (const float*)d_in[6];
    const float* Wo = (const float*)d_in[7];
    const float* bo = (const float*)d_in[8];

    float* out = (float*)d_out;
    const size_t out_elems = (size_t)MTOK * DIMC;            // 16,777,216
    float* attnp = ((size_t)out_size > out_elems) ? (out + out_elems) : nullptr;

    float* scratch = nullptr;
    cudaGetSymbolAddress((void**)&scratch, g_scratch);
    float* gq = scratch;
    float* gk = gq + out_elems;
    float* gv = gk + out_elems;
    float* go = gv + out_elems;

    dim3 gg(DIMC / 128, MTOK / 128);   // (8, 128)
    gemm_tf32_bias<<<gg, 256>>>(x, Wq, bq, gq);
    gemm_tf32_bias<<<gg, 256>>>(x, Wk, bk, gk);
    gemm_tf32_bias<<<gg, 256>>>(x, Wv, bv, gv);

    const size_t smem = (size_t)(256*64*2 + 64*64 + 64*SLD) * sizeof(float); // 214016 B
    cudaFuncSetAttribute(attn_kernel, cudaFuncAttributeMaxDynamicSharedMemorySize, (int)smem);
    attn_kernel<<<dim3(BATCH*NHEAD*NWIN, BLKT/QCH), 256, smem>>>(gq, gk, gv, go, attnp);

    gemm_tf32_bias<<<gg, 256>>>(go, Wo, bo, out);
}

// round 2
// speedup vs baseline: 1.1771x; 1.1771x over previous
#include <cuda_runtime.h>
#include <mma.h>
#include <math.h>

using namespace nvcuda;

#define BATCH 4
#define SEQ   4096
#define DIMC  1024
#define NHEAD 16
#define HDIM  64
#define NWIN  16
#define BLKT  256
#define MTOK  (BATCH*SEQ)
#define QCH   64
#define ATTN_SCALE 0.125f

#define BM 128
#define BN 128
#define BK 32
#define STAGES 3
#define LDA 36                 // padded leading dim for GEMM smem tiles
#define SLD 264                // padded leading dim for score tile (8*r+part banks distinct)

__device__ float g_scratch[4ull * MTOK * DIMC];

// ---------------- cp.async helpers ----------------
__device__ __forceinline__ void cp_async16(void* smem, const void* gmem) {
    unsigned s = (unsigned)__cvta_generic_to_shared(smem);
    asm volatile("cp.async.cg.shared.global [%0], [%1], 16;\n" :: "r"(s), "l"(gmem));
}
__device__ __forceinline__ void cp_commit() {
    asm volatile("cp.async.commit_group;\n");
}
template<int N> __device__ __forceinline__ void cp_wait() {
    asm volatile("cp.async.wait_group %0;\n" :: "n"(N));
}

// ---------------------------------------------------------------------------
// C[M,1024] = A[M,1024] @ Bw[1024,1024]^T + bias. blockIdx.z picks (W,b,C).
// 128x128 tile, BK=32, 3-stage cp.async pipeline, 8 warps (4x2), tf32 wmma.
// ---------------------------------------------------------------------------
__global__ __launch_bounds__(256) void gemm3_tf32(
    const float* __restrict__ A,
    const float* __restrict__ W0, const float* __restrict__ b0, float* __restrict__ C0,
    const float* __restrict__ W1, const float* __restrict__ b1, float* __restrict__ C1,
    const float* __restrict__ W2, const float* __restrict__ b2, float* __restrict__ C2)
{
    extern __shared__ float sm[];
    const float* Bw; const float* bias; float* C;
    if (blockIdx.z == 0)      { Bw = W0; bias = b0; C = C0; }
    else if (blockIdx.z == 1) { Bw = W1; bias = b1; C = C1; }
    else                      { Bw = W2; bias = b2; C = C2; }

    const int K = DIMC, N = DIMC;
    const int tid  = threadIdx.x;
    const int warp = tid >> 5;
    const int lane = tid & 31;
    const int wm = warp & 3;
    const int wn = warp >> 2;
    const int rowBase = blockIdx.y * BM;
    const int colBase = blockIdx.x * BN;

    // smem: per stage A[128][LDA] then B[128][LDA]
    const int stageF = BM * LDA;
    auto As = [&](int s) { return sm + (size_t)s * 2 * stageF; };
    auto Bs = [&](int s) { return sm + (size_t)s * 2 * stageF + stageF; };

    // thread -> 4 float4 loads for A, 4 for B per stage
    const int lr = tid >> 3;            // 0..31 base row
    const int lc = (tid & 7) * 4;       // 0..28 col (floats)

    auto loadStage = [&](int s, int k0) {
        float* as = As(s); float* bs = Bs(s);
        #pragma unroll
        for (int j = 0; j < 4; j++) {
            int r = lr + j * 32;
            cp_async16(&as[r * LDA + lc], &A [(size_t)(rowBase + r) * K + k0 + lc]);
            cp_async16(&bs[r * LDA + lc], &Bw[(size_t)(colBase + r) * K + k0 + lc]);
        }
        cp_commit();
    };

    wmma::fragment<wmma::accumulator,16,16,8,float> acc[2][4];
    #pragma unroll
    for (int i = 0; i < 2; i++)
        #pragma unroll
        for (int j = 0; j < 4; j++)
            wmma::fill_fragment(acc[i][j], 0.0f);

    const int NT = K / BK;              // 32
    loadStage(0, 0);
    loadStage(1, BK);

    for (int kt = 0; kt < NT; kt++) {
        cp_wait<STAGES - 2>();
        __syncthreads();
        if (kt + STAGES - 1 < NT)
            loadStage((kt + STAGES - 1) % STAGES, (kt + STAGES - 1) * BK);

        const float* as = As(kt % STAGES);
        const float* bs = Bs(kt % STAGES);
        #pragma unroll
        for (int kk = 0; kk < BK; kk += 8) {
            wmma::fragment<wmma::matrix_a,16,16,8,wmma::precision::tf32,wmma::row_major> af[2];
            wmma::fragment<wmma::matrix_b,16,16,8,wmma::precision::tf32,wmma::col_major> bf[4];
            #pragma unroll
            for (int i = 0; i < 2; i++) {
                wmma::load_matrix_sync(af[i], as + (wm*32 + i*16) * LDA + kk, LDA);
                #pragma unroll
                for (int e = 0; e < af[i].num_elements; e++)
                    af[i].x[e] = wmma::__float_to_tf32(af[i].x[e]);
            }
            #pragma unroll
            for (int j = 0; j < 4; j++) {
                wmma::load_matrix_sync(bf[j], bs + (wn*64 + j*16) * LDA + kk, LDA);
                #pragma unroll
                for (int e = 0; e < bf[j].num_elements; e++)
                    bf[j].x[e] = wmma::__float_to_tf32(bf[j].x[e]);
            }
            #pragma unroll
            for (int i = 0; i < 2; i++)
                #pragma unroll
                for (int j = 0; j < 4; j++)
                    wmma::mma_sync(acc[i][j], af[i], bf[j], acc[i][j]);
        }
        __syncthreads();
    }

    // epilogue: stage per-warp 16x16 in smem, add bias, vector store
    float* wstg = sm + warp * 352;      // 16x20 pad + slack
    #pragma unroll
    for (int i = 0; i < 2; i++) {
        #pragma unroll
        for (int j = 0; j < 4; j++) {
            wmma::store_matrix_sync(wstg, acc[i][j], 20, wmma::mem_row_major);
            __syncwarp();
            int r0 = rowBase + wm*32 + i*16;
            int c0 = colBase + wn*64 + j*16;
            int r  = lane >> 1;
            int cc = (lane & 1) * 8;
            float4 v0, v1;
            v0.x = wstg[r*20 + cc+0] + __ldg(&bias[c0+cc+0]);
            v0.y = wstg[r*20 + cc+1] + __ldg(&bias[c0+cc+1]);
            v0.z = wstg[r*20 + cc+2] + __ldg(&bias[c0+cc+2]);
            v0.w = wstg[r*20 + cc+3] + __ldg(&bias[c0+cc+3]);
            v1.x = wstg[r*20 + cc+4] + __ldg(&bias[c0+cc+4]);
            v1.y = wstg[r*20 + cc+5] + __ldg(&bias[c0+cc+5]);
            v1.z = wstg[r*20 + cc+6] + __ldg(&bias[c0+cc+6]);
            v1.w = wstg[r*20 + cc+7] + __ldg(&bias[c0+cc+7]);
            *(float4*)&C[(size_t)(r0 + r) * N + c0 + cc]     = v0;
            *(float4*)&C[(size_t)(r0 + r) * N + c0 + cc + 4] = v1;
            __syncwarp();
        }
    }
}

// ---------------------------------------------------------------------------
// Block-local attention. One CTA per (b,h,w) window, 512 threads (16 warps).
// K/V loaded once; loop over 4 q-chunks of 64 rows with cp.async Q prefetch.
// ---------------------------------------------------------------------------
__global__ __launch_bounds__(512) void attn_kernel(
    const float* __restrict__ q, const float* __restrict__ k,
    const float* __restrict__ v, float* __restrict__ o,
    float* __restrict__ attnp)
{
    extern __shared__ float sm[];
    float* Ks = sm;                    // 256*64
    float* Vs = Ks + 256*64;           // 256*64
    float* Qs = Vs + 256*64;           // 64*64
    float* Ss = Qs + 64*64;            // 64*SLD

    const int tid  = threadIdx.x;
    const int warp = tid >> 5;
    const int wm = warp >> 2;          // 0..3 : 16-row group
    const int wn = warp & 3;           // 0..3

    const int bhw = blockIdx.x;
    const int w = bhw & 15;
    const int h = (bhw >> 4) & 15;
    const int b = bhw >> 8;

    const size_t tokBase = (size_t)b * SEQ + (size_t)w * BLKT;
    const int    colBase = h * HDIM;

    const float* Kg = k + tokBase * DIMC + colBase;
    const float* Vg = v + tokBase * DIMC + colBase;
    const float* Qg = q + tokBase * DIMC + colBase;

    // load K,V (256x64) + Q chunk 0 via cp.async
    #pragma unroll
    for (int j = 0; j < 8; j++) {
        int i = tid + j * 512;         // 0..4095 float4
        int r = i >> 4, c = (i & 15) * 4;
        cp_async16(&Ks[r*64 + c], Kg + (size_t)r * DIMC + c);
        cp_async16(&Vs[r*64 + c], Vg + (size_t)r * DIMC + c);
    }
    #pragma unroll
    for (int j = 0; j < 2; j++) {
        int i = tid + j * 512;         // 0..1023 float4
        int r = i >> 4, c = (i & 15) * 4;
        cp_async16(&Qs[r*64 + c], Qg + (size_t)r * DIMC + c);
    }
    cp_commit();
    cp_wait<0>();
    __syncthreads();

    for (int qc = 0; qc < 4; qc++) {
        // ---- S = Q @ K^T : warp = 16 rows x 64 cols ----
        {
            wmma::fragment<wmma::accumulator,16,16,8,float> sacc[4];
            #pragma unroll
            for (int j = 0; j < 4; j++) wmma::fill_fragment(sacc[j], 0.0f);
            #pragma unroll
            for (int d0 = 0; d0 < HDIM; d0 += 8) {
                wmma::fragment<wmma::matrix_a,16,16,8,wmma::precision::tf32,wmma::row_major> af;
                wmma::load_matrix_sync(af, Qs + (wm*16)*HDIM + d0, HDIM);
                #pragma unroll
                for (int e = 0; e < af.num_elements; e++)
                    af.x[e] = wmma::__float_to_tf32(af.x[e]);
                #pragma unroll
                for (int j = 0; j < 4; j++) {
                    wmma::fragment<wmma::matrix_b,16,16,8,wmma::precision::tf32,wmma::col_major> bf;
                    wmma::load_matrix_sync(bf, Ks + (size_t)(wn*64 + j*16)*HDIM + d0, HDIM);
                    #pragma unroll
                    for (int e = 0; e < bf.num_elements; e++)
                        bf.x[e] = wmma::__float_to_tf32(bf.x[e]);
                    wmma::mma_sync(sacc[j], af, bf, sacc[j]);
                }
            }
            #pragma unroll
            for (int j = 0; j < 4; j++)
                wmma::store_matrix_sync(Ss + (wm*16)*SLD + wn*64 + j*16, sacc[j],
                                        SLD, wmma::mem_row_major);
        }
        __syncthreads();

        // prefetch next Q chunk (Qs no longer read this iteration)
        if (qc < 3) {
            const float* Qn = Qg + (size_t)(qc + 1) * QCH * DIMC;
            #pragma unroll
            for (int j = 0; j < 2; j++) {
                int i = tid + j * 512;
                int r = i >> 4, c = (i & 15) * 4;
                cp_async16(&Qs[r*64 + c], Qn + (size_t)r * DIMC + c);
            }
            cp_commit();
        }

        // ---- softmax: 8 threads per row, strided (bank-conflict-free) ----
        {
            const int row  = tid >> 3;
            const int part = tid & 7;
            float* srow = Ss + row * SLD;
            float mx = -1e30f;
            #pragma unroll
            for (int j = 0; j < 32; j++) mx = fmaxf(mx, srow[j*8 + part]);
            mx = fmaxf(mx, __shfl_xor_sync(0xffffffffu, mx, 1));
            mx = fmaxf(mx, __shfl_xor_sync(0xffffffffu, mx, 2));
            mx = fmaxf(mx, __shfl_xor_sync(0xffffffffu, mx, 4));
            float sum = 0.0f;
            #pragma unroll
            for (int j = 0; j < 32; j++) {
                float e = __expf((srow[j*8 + part] - mx) * ATTN_SCALE);
                srow[j*8 + part] = e;
                sum += e;
            }
            sum += __shfl_xor_sync(0xffffffffu, sum, 1);
            sum += __shfl_xor_sync(0xffffffffu, sum, 2);
            sum += __shfl_xor_sync(0xffffffffu, sum, 4);
            const float inv = 1.0f / sum;
            if (attnp) {
                float* arow = attnp + ((((size_t)b*NHEAD + h)*NWIN + w)*BLKT
                                       + qc*QCH + row) * BLKT;
                #pragma unroll
                for (int j = 0; j < 32; j++) {
                    float p = srow[j*8 + part] * inv;
                    srow[j*8 + part] = p;
                    __stcs(&arow[j*8 + part], p);
                }
            } else {
                #pragma unroll
                for (int j = 0; j < 32; j++)
                    srow[j*8 + part] *= inv;
            }
        }
        __syncthreads();

        // ---- O = P @ V : each warp 16x16 output tile ----
        {
            wmma::fragment<wmma::accumulator,16,16,8,float> oacc;
            wmma::fill_fragment(oacc, 0.0f);
            #pragma unroll 8
            for (int k0 = 0; k0 < BLKT; k0 += 8) {
                wmma::fragment<wmma::matrix_a,16,16,8,wmma::precision::tf32,wmma::row_major> af;
                wmma::load_matrix_sync(af, Ss + (wm*16)*SLD + k0, SLD);
                #pragma unroll
                for (int e = 0; e < af.num_elements; e++)
                    af.x[e] = wmma::__float_to_tf32(af.x[e]);
                wmma::fragment<wmma::matrix_b,16,16,8,wmma::precision::tf32,wmma::row_major> bf;
                wmma::load_matrix_sync(bf, Vs + (size_t)k0*HDIM + wn*16, HDIM);
                #pragma unroll
                for (int e = 0; e < bf.num_elements; e++)
                    bf.x[e] = wmma::__float_to_tf32(bf.x[e]);
                wmma::mma_sync(oacc, af, bf, oacc);
            }
            float* optr = o + (tokBase + (size_t)qc*QCH + wm*16) * DIMC
                            + colBase + wn*16;
            wmma::store_matrix_sync(optr, oacc, DIMC, wmma::mem_row_major);
        }

        if (qc < 3) cp_wait<0>();
        __syncthreads();
    }
}

// ---------------------------------------------------------------------------
extern "C" void kernel_launch(void* const* d_in, const int* in_sizes, int n_in,
                              void* d_out, int out_size)
{
    const float* x  = (const float*)d_in[0];
    const float* Wq = (const float*)d_in[1];
    const float* bq = (const float*)d_in[2];
    const float* Wk = (const float*)d_in[3];
    const float* bk = (const float*)d_in[4];
    const float* Wv = (const float*)d_in[5];
    const float* bv = (const float*)d_in[6];
    const float* Wo = (const float*)d_in[7];
    const float* bo = (const float*)d_in[8];

    float* out = (float*)d_out;
    const size_t out_elems = (size_t)MTOK * DIMC;
    float* attnp = ((size_t)out_size > out_elems) ? (out + out_elems) : nullptr;

    float* scratch = nullptr;
    cudaGetSymbolAddress((void**)&scratch, g_scratch);
    float* gq = scratch;
    float* gk = gq + out_elems;
    float* gv = gk + out_elems;
    float* go = gv + out_elems;

    const size_t gemm_smem = (size_t)STAGES * 2 * BM * LDA * sizeof(float); // 110592
    static int cfg_done = 0;
    cudaFuncSetAttribute(gemm3_tf32, cudaFuncAttributeMaxDynamicSharedMemorySize, (int)gemm_smem);

    dim3 gg(DIMC / BN, MTOK / BM, 3);
    gemm3_tf32<<<gg, 256, gemm_smem>>>(x, Wq, bq, gq, Wk, bk, gk, Wv, bv, gv);

    const size_t attn_smem = (size_t)(256*64*2 + 64*64 + 64*SLD) * sizeof(float); // 215040
    cudaFuncSetAttribute(attn_kernel, cudaFuncAttributeMaxDynamicSharedMemorySize, (int)attn_smem);
    attn_kernel<<<BATCH*NHEAD*NWIN, 512, attn_smem>>>(gq, gk, gv, go, attnp);

    dim3 go_grid(DIMC / BN, MTOK / BM, 1);
    gemm3_tf32<<<go_grid, 256, gemm_smem>>>(go, Wo, bo, out, Wo, bo, out, Wo, bo, out);
    (void)cfg_done;
}

// round 4
// speedup vs baseline: 1.3159x; 1.1179x over previous
#include <cuda_runtime.h>
#include <mma.h>
#include <math.h>
#include <stdint.h>

using namespace nvcuda;

#define BATCH 4
#define SEQ   4096
#define DIMC  1024
#define NHEAD 16
#define HDIM  64
#define NWIN  16
#define BLKT  256
#define MTOK  (BATCH*SEQ)
#define QCH   64
#define ATTN_SCALE 0.125f
#define SLD 264

#define BM 128
#define BN 128
#define BK 32
#define STAGES 2
#define LDA 36

// scratch: xr, q, k, v, go (5 x 16M) + 4 rounded weights
__device__ float g_scratch[5ull * MTOK * DIMC + 4ull * DIMC * DIMC];

// ---------------- helpers ----------------
__device__ __forceinline__ void cp_async16(void* smem, const void* gmem) {
    unsigned s = (unsigned)__cvta_generic_to_shared(smem);
    asm volatile("cp.async.cg.shared.global [%0], [%1], 16;\n" :: "r"(s), "l"(gmem));
}
__device__ __forceinline__ void cp_commit() {
    asm volatile("cp.async.commit_group;\n");
}
template<int N> __device__ __forceinline__ void cp_wait() {
    asm volatile("cp.async.wait_group %0;\n" :: "n"(N));
}
__device__ __forceinline__ float round_tf32(float x) {
    uint32_t u;
    asm("cvt.rna.tf32.f32 %0, %1;" : "=r"(u) : "f"(x));
    return __uint_as_float(u);
}

// ---------------------------------------------------------------------------
// tf32-RN rounding prepass
// ---------------------------------------------------------------------------
__global__ void round_tf32_kernel(const float4* __restrict__ src,
                                  float4* __restrict__ dst, int n4) {
    int i = blockIdx.x * blockDim.x + threadIdx.x;
    if (i >= n4) return;
    float4 v = src[i];
    v.x = round_tf32(v.x); v.y = round_tf32(v.y);
    v.z = round_tf32(v.z); v.w = round_tf32(v.w);
    dst[i] = v;
}

// ---------------------------------------------------------------------------
// C[M,1024] = A[M,1024] @ W[1024,1024]^T + bias.  A, W pre-rounded to tf32.
// 128x128 tile, BK=32, 2-stage cp.async pipeline, 2 CTAs/SM, no in-loop cvt.
// roundOut!=0 -> round result to tf32 (for q,k,v feeding later tf32 GEMMs).
// ---------------------------------------------------------------------------
__global__ __launch_bounds__(256, 2) void gemm3_tf32(
    const float* __restrict__ A,
    const float* __restrict__ W0, const float* __restrict__ b0, float* __restrict__ C0,
    const float* __restrict__ W1, const float* __restrict__ b1, float* __restrict__ C1,
    const float* __restrict__ W2, const float* __restrict__ b2, float* __restrict__ C2,
    int roundOut)
{
    extern __shared__ float sm[];
    const float* Bw; const float* bias; float* C;
    if (blockIdx.z == 0)      { Bw = W0; bias = b0; C = C0; }
    else if (blockIdx.z == 1) { Bw = W1; bias = b1; C = C1; }
    else                      { Bw = W2; bias = b2; C = C2; }

    const int K = DIMC, N = DIMC;
    const int tid  = threadIdx.x;
    const int warp = tid >> 5;
    const int lane = tid & 31;
    const int wm = warp & 3;
    const int wn = warp >> 2;
    const int rowBase = blockIdx.y * BM;
    const int colBase = blockIdx.x * BN;

    const int stageF = BM * LDA;
    auto As = [&](int s) { return sm + (size_t)s * 2 * stageF; };
    auto Bs = [&](int s) { return sm + (size_t)s * 2 * stageF + stageF; };

    const int lr = tid >> 3;
    const int lc = (tid & 7) * 4;

    auto loadStage = [&](int s, int kt) {
        float* as = As(s); float* bs = Bs(s);
        int k0 = kt * BK;
        #pragma unroll
        for (int j = 0; j < 4; j++) {
            int r = lr + j * 32;
            cp_async16(&as[r * LDA + lc], &A [(size_t)(rowBase + r) * K + k0 + lc]);
            cp_async16(&bs[r * LDA + lc], &Bw[(size_t)(colBase + r) * K + k0 + lc]);
        }
        cp_commit();
    };

    wmma::fragment<wmma::accumulator,16,16,8,float> acc[2][4];
    #pragma unroll
    for (int i = 0; i < 2; i++)
        #pragma unroll
        for (int j = 0; j < 4; j++)
            wmma::fill_fragment(acc[i][j], 0.0f);

    const int NT = K / BK;              // 32
    loadStage(0, 0);

    for (int kt = 0; kt < NT; kt++) {
        if (kt + 1 < NT) {
            loadStage((kt + 1) & 1, kt + 1);
            cp_wait<1>();
        } else {
            cp_wait<0>();
        }
        __syncthreads();

        const float* as = As(kt & 1);
        const float* bs = Bs(kt & 1);
        #pragma unroll
        for (int kk = 0; kk < BK; kk += 8) {
            wmma::fragment<wmma::matrix_a,16,16,8,wmma::precision::tf32,wmma::row_major> af[2];
            wmma::fragment<wmma::matrix_b,16,16,8,wmma::precision::tf32,wmma::col_major> bf[4];
            #pragma unroll
            for (int i = 0; i < 2; i++)
                wmma::load_matrix_sync(af[i], as + (wm*32 + i*16) * LDA + kk, LDA);
            #pragma unroll
            for (int j = 0; j < 4; j++)
                wmma::load_matrix_sync(bf[j], bs + (wn*64 + j*16) * LDA + kk, LDA);
            #pragma unroll
            for (int i = 0; i < 2; i++)
                #pragma unroll
                for (int j = 0; j < 4; j++)
                    wmma::mma_sync(acc[i][j], af[i], bf[j], acc[i][j]);
        }
        __syncthreads();
    }

    // epilogue
    float* wstg = sm + warp * 352;
    #pragma unroll
    for (int i = 0; i < 2; i++) {
        #pragma unroll
        for (int j = 0; j < 4; j++) {
            wmma::store_matrix_sync(wstg, acc[i][j], 20, wmma::mem_row_major);
            __syncwarp();
            int r0 = rowBase + wm*32 + i*16;
            int c0 = colBase + wn*64 + j*16;
            int r  = lane >> 1;
            int cc = (lane & 1) * 8;
            float o[8];
            #pragma unroll
            for (int t = 0; t < 8; t++)
                o[t] = wstg[r*20 + cc + t] + __ldg(&bias[c0 + cc + t]);
            if (roundOut) {
                #pragma unroll
                for (int t = 0; t < 8; t++) o[t] = round_tf32(o[t]);
            }
            *(float4*)&C[(size_t)(r0 + r) * N + c0 + cc]     = *(float4*)&o[0];
            *(float4*)&C[(size_t)(r0 + r) * N + c0 + cc + 4] = *(float4*)&o[4];
            __syncwarp();
        }
    }
}

// ---------------------------------------------------------------------------
// Block-local attention. One CTA per window, 512 threads. q,k,v pre-rounded
// tf32 -> no in-loop cvt; P rounded to tf32 in softmax before PV matmul.
// ---------------------------------------------------------------------------
__global__ __launch_bounds__(512) void attn_kernel(
    const float* __restrict__ q, const float* __restrict__ k,
    const float* __restrict__ v, float* __restrict__ o,
    float* __restrict__ attnp)
{
    extern __shared__ float sm[];
    float* Ks = sm;
    float* Vs = Ks + 256*64;
    float* Qs = Vs + 256*64;
    float* Ss = Qs + 64*64;

    const int tid  = threadIdx.x;
    const int warp = tid >> 5;
    const int wm = warp >> 2;
    const int wn = warp & 3;

    const int bhw = blockIdx.x;
    const int w = bhw & 15;
    const int h = (bhw >> 4) & 15;
    const int b = bhw >> 8;

    const size_t tokBase = (size_t)b * SEQ + (size_t)w * BLKT;
    const int    colBase = h * HDIM;

    const float* Kg = k + tokBase * DIMC + colBase;
    const float* Vg = v + tokBase * DIMC + colBase;
    const float* Qg = q + tokBase * DIMC + colBase;

    #pragma unroll
    for (int j = 0; j < 8; j++) {
        int i = tid + j * 512;
        int r = i >> 4, c = (i & 15) * 4;
        cp_async16(&Ks[r*64 + c], Kg + (size_t)r * DIMC + c);
        cp_async16(&Vs[r*64 + c], Vg + (size_t)r * DIMC + c);
    }
    #pragma unroll
    for (int j = 0; j < 2; j++) {
        int i = tid + j * 512;
        int r = i >> 4, c = (i & 15) * 4;
        cp_async16(&Qs[r*64 + c], Qg + (size_t)r * DIMC + c);
    }
    cp_commit();
    cp_wait<0>();
    __syncthreads();

    for (int qc = 0; qc < 4; qc++) {
        // ---- S = Q @ K^T ----
        {
            wmma::fragment<wmma::accumulator,16,16,8,float> sacc[4];
            #pragma unroll
            for (int j = 0; j < 4; j++) wmma::fill_fragment(sacc[j], 0.0f);
            #pragma unroll
            for (int d0 = 0; d0 < HDIM; d0 += 8) {
                wmma::fragment<wmma::matrix_a,16,16,8,wmma::precision::tf32,wmma::row_major> af;
                wmma::load_matrix_sync(af, Qs + (wm*16)*HDIM + d0, HDIM);
                #pragma unroll
                for (int j = 0; j < 4; j++) {
                    wmma::fragment<wmma::matrix_b,16,16,8,wmma::precision::tf32,wmma::col_major> bf;
                    wmma::load_matrix_sync(bf, Ks + (size_t)(wn*64 + j*16)*HDIM + d0, HDIM);
                    wmma::mma_sync(sacc[j], af, bf, sacc[j]);
                }
            }
            #pragma unroll
            for (int j = 0; j < 4; j++)
                wmma::store_matrix_sync(Ss + (wm*16)*SLD + wn*64 + j*16, sacc[j],
                                        SLD, wmma::mem_row_major);
        }
        __syncthreads();

        if (qc < 3) {
            const float* Qn = Qg + (size_t)(qc + 1) * QCH * DIMC;
            #pragma unroll
            for (int j = 0; j < 2; j++) {
                int i = tid + j * 512;
                int r = i >> 4, c = (i & 15) * 4;
                cp_async16(&Qs[r*64 + c], Qn + (size_t)r * DIMC + c);
            }
            cp_commit();
        }

        // ---- softmax ----
        {
            const int row  = tid >> 3;
            const int part = tid & 7;
            float* srow = Ss + row * SLD;
            float mx = -1e30f;
            #pragma unroll
            for (int j = 0; j < 32; j++) mx = fmaxf(mx, srow[j*8 + part]);
            mx = fmaxf(mx, __shfl_xor_sync(0xffffffffu, mx, 1));
            mx = fmaxf(mx, __shfl_xor_sync(0xffffffffu, mx, 2));
            mx = fmaxf(mx, __shfl_xor_sync(0xffffffffu, mx, 4));
            float sum = 0.0f;
            #pragma unroll
            for (int j = 0; j < 32; j++) {
                float e = __expf((srow[j*8 + part] - mx) * ATTN_SCALE);
                srow[j*8 + part] = e;
                sum += e;
            }
            sum += __shfl_xor_sync(0xffffffffu, sum, 1);
            sum += __shfl_xor_sync(0xffffffffu, sum, 2);
            sum += __shfl_xor_sync(0xffffffffu, sum, 4);
            const float inv = 1.0f / sum;
            if (attnp) {
                float* arow = attnp + ((((size_t)b*NHEAD + h)*NWIN + w)*BLKT
                                       + qc*QCH + row) * BLKT;
                #pragma unroll
                for (int j = 0; j < 32; j++) {
                    float p = srow[j*8 + part] * inv;
                    __stcs(&arow[j*8 + part], p);
                    srow[j*8 + part] = round_tf32(p);
                }
            } else {
                #pragma unroll
                for (int j = 0; j < 32; j++)
                    srow[j*8 + part] = round_tf32(srow[j*8 + part] * inv);
            }
        }
        __syncthreads();

        // ---- O = P @ V ----
        {
            wmma::fragment<wmma::accumulator,16,16,8,float> oacc;
            wmma::fill_fragment(oacc, 0.0f);
            #pragma unroll 8
            for (int k0 = 0; k0 < BLKT; k0 += 8) {
                wmma::fragment<wmma::matrix_a,16,16,8,wmma::precision::tf32,wmma::row_major> af;
                wmma::load_matrix_sync(af, Ss + (wm*16)*SLD + k0, SLD);
                wmma::fragment<wmma::matrix_b,16,16,8,wmma::precision::tf32,wmma::row_major> bf;
                wmma::load_matrix_sync(bf, Vs + (size_t)k0*HDIM + wn*16, HDIM);
                wmma::mma_sync(oacc, af, bf, oacc);
            }
            float* optr = o + (tokBase + (size_t)qc*QCH + wm*16) * DIMC
                            + colBase + wn*16;
            wmma::store_matrix_sync(optr, oacc, DIMC, wmma::mem_row_major);
        }

        if (qc < 3) cp_wait<0>();
        __syncthreads();
    }
}

// ---------------------------------------------------------------------------
extern "C" void kernel_launch(void* const* d_in, const int* in_sizes, int n_in,
                              void* d_out, int out_size)
{
    const float* x  = (const float*)d_in[0];
    const float* Wq = (const float*)d_in[1];
    const float* bq = (const float*)d_in[2];
    const float* Wk = (const float*)d_in[3];
    const float* bk = (const float*)d_in[4];
    const float* Wv = (const float*)d_in[5];
    const float* bv = (const float*)d_in[6];
    const float* Wo = (const float*)d_in[7];
    const float* bo = (const float*)d_in[8];

    float* out = (float*)d_out;
    const size_t out_elems = (size_t)MTOK * DIMC;
    float* attnp = ((size_t)out_size > out_elems) ? (out + out_elems) : nullptr;

    float* scratch = nullptr;
    cudaGetSymbolAddress((void**)&scratch, g_scratch);
    float* xr = scratch;
    float* gq = xr + out_elems;
    float* gk = gq + out_elems;
    float* gv = gk + out_elems;
    float* go = gv + out_elems;
    float* wr = go + out_elems;
    const size_t wsz = (size_t)DIMC * DIMC;
    float* wrq = wr;
    float* wrk = wr + wsz;
    float* wrv = wr + 2*wsz;
    float* wro = wr + 3*wsz;

    round_tf32_kernel<<<(int)(out_elems/4/256), 256>>>((const float4*)x,  (float4*)xr,  (int)(out_elems/4));
    round_tf32_kernel<<<(int)(wsz/4/256),       256>>>((const float4*)Wq, (float4*)wrq, (int)(wsz/4));
    round_tf32_kernel<<<(int)(wsz/4/256),       256>>>((const float4*)Wk, (float4*)wrk, (int)(wsz/4));
    round_tf32_kernel<<<(int)(wsz/4/256),       256>>>((const float4*)Wv, (float4*)wrv, (int)(wsz/4));
    round_tf32_kernel<<<(int)(wsz/4/256),       256>>>((const float4*)Wo, (float4*)wro, (int)(wsz/4));

    const size_t gemm_smem = (size_t)STAGES * 2 * BM * LDA * sizeof(float); // 73728
    cudaFuncSetAttribute(gemm3_tf32, cudaFuncAttributeMaxDynamicSharedMemorySize, (int)gemm_smem);

    dim3 gg(DIMC / BN, MTOK / BM, 3);
    gemm3_tf32<<<gg, 256, gemm_smem>>>(xr, wrq, bq, gq, wrk, bk, gk, wrv, bv, gv, 1);

    const size_t attn_smem = (size_t)(256*64*2 + 64*64 + 64*SLD) * sizeof(float);
    cudaFuncSetAttribute(attn_kernel, cudaFuncAttributeMaxDynamicSharedMemorySize, (int)attn_smem);
    attn_kernel<<<BATCH*NHEAD*NWIN, 512, attn_smem>>>(gq, gk, gv, go, attnp);

    round_tf32_kernel<<<(int)(out_elems/4/256), 256>>>((const float4*)go, (float4*)go, (int)(out_elems/4));

    dim3 go_grid(DIMC / BN, MTOK / BM, 1);
    gemm3_tf32<<<go_grid, 256, gemm_smem>>>(go, wro, bo, out, wro, bo, out, wro, bo, out, 0);
}

// round 5
// speedup vs baseline: 1.3450x; 1.0221x over previous
#include <cuda_runtime.h>
#include <mma.h>
#include <math.h>
#include <stdint.h>

using namespace nvcuda;

#define BATCH 4
#define SEQ   4096
#define DIMC  1024
#define NHEAD 16
#define HDIM  64
#define NWIN  16
#define BLKT  256
#define MTOK  (BATCH*SEQ)
#define QCH   64
#define ATTN_SCALE 0.125f
#define SLD 264

#define BM 128
#define BN 128
#define BK 32
#define STAGES 3
#define LDA 36

// scratch: xr, q, k, v, go (5 x 16M) + 4 rounded weights
__device__ float g_scratch[5ull * MTOK * DIMC + 4ull * DIMC * DIMC];

// ---------------- helpers ----------------
__device__ __forceinline__ void cp_async16(void* smem, const void* gmem) {
    unsigned s = (unsigned)__cvta_generic_to_shared(smem);
    asm volatile("cp.async.cg.shared.global [%0], [%1], 16;\n" :: "r"(s), "l"(gmem));
}
__device__ __forceinline__ void cp_commit() {
    asm volatile("cp.async.commit_group;\n");
}
template<int N> __device__ __forceinline__ void cp_wait() {
    asm volatile("cp.async.wait_group %0;\n" :: "n"(N));
}
__device__ __forceinline__ float round_tf32(float x) {
    uint32_t u;
    asm("cvt.rna.tf32.f32 %0, %1;" : "=r"(u) : "f"(x));
    return __uint_as_float(u);
}

// ---------------------------------------------------------------------------
// tf32-RN rounding prepass
// ---------------------------------------------------------------------------
__global__ void round_tf32_kernel(const float4* __restrict__ src,
                                  float4* __restrict__ dst, int n4) {
    int i = blockIdx.x * blockDim.x + threadIdx.x;
    if (i >= n4) return;
    float4 v = src[i];
    v.x = round_tf32(v.x); v.y = round_tf32(v.y);
    v.z = round_tf32(v.z); v.w = round_tf32(v.w);
    dst[i] = v;
}

// ---------------------------------------------------------------------------
// C[M,1024] = A[M,1024] @ W[1024,1024]^T + bias.  A, W pre-rounded to tf32.
// 128x128 tile, BK=32, 3-stage cp.async pipeline, ONE sync per K-tile,
// 2 CTAs/SM. roundOut!=0 -> round result to tf32.
// ---------------------------------------------------------------------------
__global__ __launch_bounds__(256, 2) void gemm3_tf32(
    const float* __restrict__ A,
    const float* __restrict__ W0, const float* __restrict__ b0, float* __restrict__ C0,
    const float* __restrict__ W1, const float* __restrict__ b1, float* __restrict__ C1,
    const float* __restrict__ W2, const float* __restrict__ b2, float* __restrict__ C2,
    int roundOut)
{
    extern __shared__ float sm[];
    const float* Bw; const float* bias; float* C;
    if (blockIdx.z == 0)      { Bw = W0; bias = b0; C = C0; }
    else if (blockIdx.z == 1) { Bw = W1; bias = b1; C = C1; }
    else                      { Bw = W2; bias = b2; C = C2; }

    const int K = DIMC, N = DIMC;
    const int tid  = threadIdx.x;
    const int warp = tid >> 5;
    const int lane = tid & 31;
    const int wm = warp & 3;
    const int wn = warp >> 2;
    const int rowBase = blockIdx.y * BM;
    const int colBase = blockIdx.x * BN;

    const int stageF = BM * LDA;
    auto As = [&](int s) { return sm + (size_t)s * 2 * stageF; };
    auto Bs = [&](int s) { return sm + (size_t)s * 2 * stageF + stageF; };

    const int lr = tid >> 3;
    const int lc = (tid & 7) * 4;

    auto loadStage = [&](int s, int kt) {
        float* as = As(s); float* bs = Bs(s);
        int k0 = kt * BK;
        #pragma unroll
        for (int j = 0; j < 4; j++) {
            int r = lr + j * 32;
            cp_async16(&as[r * LDA + lc], &A [(size_t)(rowBase + r) * K + k0 + lc]);
            cp_async16(&bs[r * LDA + lc], &Bw[(size_t)(colBase + r) * K + k0 + lc]);
        }
        cp_commit();
    };

    wmma::fragment<wmma::accumulator,16,16,8,float> acc[2][4];
    #pragma unroll
    for (int i = 0; i < 2; i++)
        #pragma unroll
        for (int j = 0; j < 4; j++)
            wmma::fill_fragment(acc[i][j], 0.0f);

    const int NT = K / BK;              // 32
    loadStage(0, 0);
    loadStage(1, 1);

    for (int kt = 0; kt < NT; kt++) {
        if (kt + 1 < NT) cp_wait<1>();
        else             cp_wait<0>();
        __syncthreads();
        // stage (kt+2)%3 was computed at iteration kt-1; the sync above makes
        // it safe to overwrite. Load overlaps compute of stage kt%3.
        if (kt + 2 < NT) loadStage((kt + 2) % STAGES, kt + 2);

        const float* as = As(kt % STAGES);
        const float* bs = Bs(kt % STAGES);
        #pragma unroll
        for (int kk = 0; kk < BK; kk += 8) {
            wmma::fragment<wmma::matrix_a,16,16,8,wmma::precision::tf32,wmma::row_major> af[2];
            wmma::fragment<wmma::matrix_b,16,16,8,wmma::precision::tf32,wmma::col_major> bf[4];
            #pragma unroll
            for (int i = 0; i < 2; i++)
                wmma::load_matrix_sync(af[i], as + (wm*32 + i*16) * LDA + kk, LDA);
            #pragma unroll
            for (int j = 0; j < 4; j++)
                wmma::load_matrix_sync(bf[j], bs + (wn*64 + j*16) * LDA + kk, LDA);
            #pragma unroll
            for (int i = 0; i < 2; i++)
                #pragma unroll
                for (int j = 0; j < 4; j++)
                    wmma::mma_sync(acc[i][j], af[i], bf[j], acc[i][j]);
        }
    }
    __syncthreads();

    // epilogue
    float* wstg = sm + warp * 352;
    #pragma unroll
    for (int i = 0; i < 2; i++) {
        #pragma unroll
        for (int j = 0; j < 4; j++) {
            wmma::store_matrix_sync(wstg, acc[i][j], 20, wmma::mem_row_major);
            __syncwarp();
            int r0 = rowBase + wm*32 + i*16;
            int c0 = colBase + wn*64 + j*16;
            int r  = lane >> 1;
            int cc = (lane & 1) * 8;
            float o[8];
            #pragma unroll
            for (int t = 0; t < 8; t++)
                o[t] = wstg[r*20 + cc + t] + __ldg(&bias[c0 + cc + t]);
            if (roundOut) {
                #pragma unroll
                for (int t = 0; t < 8; t++) o[t] = round_tf32(o[t]);
            }
            *(float4*)&C[(size_t)(r0 + r) * N + c0 + cc]     = *(float4*)&o[0];
            *(float4*)&C[(size_t)(r0 + r) * N + c0 + cc + 4] = *(float4*)&o[4];
            __syncwarp();
        }
    }
}

// ---------------------------------------------------------------------------
// Block-local attention. One CTA per window, 512 threads. q,k,v pre-rounded
// tf32. P rounded in softmax; O rounded in epilogue (feeds tf32 Wo GEMM).
// ---------------------------------------------------------------------------
__global__ __launch_bounds__(512) void attn_kernel(
    const float* __restrict__ q, const float* __restrict__ k,
    const float* __restrict__ v, float* __restrict__ o,
    float* __restrict__ attnp)
{
    extern __shared__ float sm[];
    float* Ks = sm;
    float* Vs = Ks + 256*64;
    float* Qs = Vs + 256*64;
    float* Ss = Qs + 64*64;

    const int tid  = threadIdx.x;
    const int warp = tid >> 5;
    const int wm = warp >> 2;
    const int wn = warp & 3;

    const int bhw = blockIdx.x;
    const int w = bhw & 15;
    const int h = (bhw >> 4) & 15;
    const int b = bhw >> 8;

    const size_t tokBase = (size_t)b * SEQ + (size_t)w * BLKT;
    const int    colBase = h * HDIM;

    const float* Kg = k + tokBase * DIMC + colBase;
    const float* Vg = v + tokBase * DIMC + colBase;
    const float* Qg = q + tokBase * DIMC + colBase;

    #pragma unroll
    for (int j = 0; j < 8; j++) {
        int i = tid + j * 512;
        int r = i >> 4, c = (i & 15) * 4;
        cp_async16(&Ks[r*64 + c], Kg + (size_t)r * DIMC + c);
        cp_async16(&Vs[r*64 + c], Vg + (size_t)r * DIMC + c);
    }
    #pragma unroll
    for (int j = 0; j < 2; j++) {
        int i = tid + j * 512;
        int r = i >> 4, c = (i & 15) * 4;
        cp_async16(&Qs[r*64 + c], Qg + (size_t)r * DIMC + c);
    }
    cp_commit();
    cp_wait<0>();
    __syncthreads();

    for (int qc = 0; qc < 4; qc++) {
        // ---- S = Q @ K^T ----
        {
            wmma::fragment<wmma::accumulator,16,16,8,float> sacc[4];
            #pragma unroll
            for (int j = 0; j < 4; j++) wmma::fill_fragment(sacc[j], 0.0f);
            #pragma unroll
            for (int d0 = 0; d0 < HDIM; d0 += 8) {
                wmma::fragment<wmma::matrix_a,16,16,8,wmma::precision::tf32,wmma::row_major> af;
                wmma::load_matrix_sync(af, Qs + (wm*16)*HDIM + d0, HDIM);
                #pragma unroll
                for (int j = 0; j < 4; j++) {
                    wmma::fragment<wmma::matrix_b,16,16,8,wmma::precision::tf32,wmma::col_major> bf;
                    wmma::load_matrix_sync(bf, Ks + (size_t)(wn*64 + j*16)*HDIM + d0, HDIM);
                    wmma::mma_sync(sacc[j], af, bf, sacc[j]);
                }
            }
            #pragma unroll
            for (int j = 0; j < 4; j++)
                wmma::store_matrix_sync(Ss + (wm*16)*SLD + wn*64 + j*16, sacc[j],
                                        SLD, wmma::mem_row_major);
        }
        __syncthreads();

        if (qc < 3) {
            const float* Qn = Qg + (size_t)(qc + 1) * QCH * DIMC;
            #pragma unroll
            for (int j = 0; j < 2; j++) {
                int i = tid + j * 512;
                int r = i >> 4, c = (i & 15) * 4;
                cp_async16(&Qs[r*64 + c], Qn + (size_t)r * DIMC + c);
            }
            cp_commit();
        }

        // ---- softmax ----
        {
            const int row  = tid >> 3;
            const int part = tid & 7;
            float* srow = Ss + row * SLD;
            float mx = -1e30f;
            #pragma unroll
            for (int j = 0; j < 32; j++) mx = fmaxf(mx, srow[j*8 + part]);
            mx = fmaxf(mx, __shfl_xor_sync(0xffffffffu, mx, 1));
            mx = fmaxf(mx, __shfl_xor_sync(0xffffffffu, mx, 2));
            mx = fmaxf(mx, __shfl_xor_sync(0xffffffffu, mx, 4));
            float sum = 0.0f;
            #pragma unroll
            for (int j = 0; j < 32; j++) {
                float e = __expf((srow[j*8 + part] - mx) * ATTN_SCALE);
                srow[j*8 + part] = e;
                sum += e;
            }
            sum += __shfl_xor_sync(0xffffffffu, sum, 1);
            sum += __shfl_xor_sync(0xffffffffu, sum, 2);
            sum += __shfl_xor_sync(0xffffffffu, sum, 4);
            const float inv = 1.0f / sum;
            if (attnp) {
                float* arow = attnp + ((((size_t)b*NHEAD + h)*NWIN + w)*BLKT
                                       + qc*QCH + row) * BLKT;
                #pragma unroll
                for (int j = 0; j < 32; j++) {
                    float p = srow[j*8 + part] * inv;
                    __stcs(&arow[j*8 + part], p);
                    srow[j*8 + part] = round_tf32(p);
                }
            } else {
                #pragma unroll
                for (int j = 0; j < 32; j++)
                    srow[j*8 + part] = round_tf32(srow[j*8 + part] * inv);
            }
        }
        __syncthreads();

        // ---- O = P @ V (output rounded to tf32 for the Wo GEMM) ----
        {
            wmma::fragment<wmma::accumulator,16,16,8,float> oacc;
            wmma::fill_fragment(oacc, 0.0f);
            #pragma unroll 8
            for (int k0 = 0; k0 < BLKT; k0 += 8) {
                wmma::fragment<wmma::matrix_a,16,16,8,wmma::precision::tf32,wmma::row_major> af;
                wmma::load_matrix_sync(af, Ss + (wm*16)*SLD + k0, SLD);
                wmma::fragment<wmma::matrix_b,16,16,8,wmma::precision::tf32,wmma::row_major> bf;
                wmma::load_matrix_sync(bf, Vs + (size_t)k0*HDIM + wn*16, HDIM);
                wmma::mma_sync(oacc, af, bf, oacc);
            }
            #pragma unroll
            for (int e = 0; e < oacc.num_elements; e++)
                oacc.x[e] = round_tf32(oacc.x[e]);
            float* optr = o + (tokBase + (size_t)qc*QCH + wm*16) * DIMC
                            + colBase + wn*16;
            wmma::store_matrix_sync(optr, oacc, DIMC, wmma::mem_row_major);
        }

        if (qc < 3) cp_wait<0>();
        __syncthreads();
    }
}

// ---------------------------------------------------------------------------
extern "C" void kernel_launch(void* const* d_in, const int* in_sizes, int n_in,
                              void* d_out, int out_size)
{
    const float* x  = (const float*)d_in[0];
    const float* Wq = (const float*)d_in[1];
    const float* bq = (const float*)d_in[2];
    const float* Wk = (const float*)d_in[3];
    const float* bk = (const float*)d_in[4];
    const float* Wv = (const float*)d_in[5];
    const float* bv = (const float*)d_in[6];
    const float* Wo = (const float*)d_in[7];
    const float* bo = (const float*)d_in[8];

    float* out = (float*)d_out;
    const size_t out_elems = (size_t)MTOK * DIMC;
    float* attnp = ((size_t)out_size > out_elems) ? (out + out_elems) : nullptr;

    float* scratch = nullptr;
    cudaGetSymbolAddress((void**)&scratch, g_scratch);
    float* xr = scratch;
    float* gq = xr + out_elems;
    float* gk = gq + out_elems;
    float* gv = gk + out_elems;
    float* go = gv + out_elems;
    float* wr = go + out_elems;
    const size_t wsz = (size_t)DIMC * DIMC;
    float* wrq = wr;
    float* wrk = wr + wsz;
    float* wrv = wr + 2*wsz;
    float* wro = wr + 3*wsz;

    round_tf32_kernel<<<(int)(out_elems/4/256), 256>>>((const float4*)x,  (float4*)xr,  (int)(out_elems/4));
    round_tf32_kernel<<<(int)(wsz/4/256),       256>>>((const float4*)Wq, (float4*)wrq, (int)(wsz/4));
    round_tf32_kernel<<<(int)(wsz/4/256),       256>>>((const float4*)Wk, (float4*)wrk, (int)(wsz/4));
    round_tf32_kernel<<<(int)(wsz/4/256),       256>>>((const float4*)Wv, (float4*)wrv, (int)(wsz/4));
    round_tf32_kernel<<<(int)(wsz/4/256),       256>>>((const float4*)Wo, (float4*)wro, (int)(wsz/4));

    const size_t gemm_smem = (size_t)STAGES * 2 * BM * LDA * sizeof(float); // 110592
    cudaFuncSetAttribute(gemm3_tf32, cudaFuncAttributeMaxDynamicSharedMemorySize, (int)gemm_smem);

    dim3 gg(DIMC / BN, MTOK / BM, 3);
    gemm3_tf32<<<gg, 256, gemm_smem>>>(xr, wrq, bq, gq, wrk, bk, gk, wrv, bv, gv, 1);

    const size_t attn_smem = (size_t)(256*64*2 + 64*64 + 64*SLD) * sizeof(float);
    cudaFuncSetAttribute(attn_kernel, cudaFuncAttributeMaxDynamicSharedMemorySize, (int)attn_smem);
    attn_kernel<<<BATCH*NHEAD*NWIN, 512, attn_smem>>>(gq, gk, gv, go, attnp);

    dim3 go_grid(DIMC / BN, MTOK / BM, 1);
    gemm3_tf32<<<go_grid, 256, gemm_smem>>>(go, wro, bo, out, wro, bo, out, wro, bo, out, 0);
}

// round 6
// speedup vs baseline: 1.3752x; 1.0225x over previous
#include <cuda_runtime.h>
#include <mma.h>
#include <math.h>
#include <stdint.h>

using namespace nvcuda;

#define BATCH 4
#define SEQ   4096
#define DIMC  1024
#define NHEAD 16
#define HDIM  64
#define NWIN  16
#define BLKT  256
#define MTOK  (BATCH*SEQ)
#define QCH   64
#define ATTN_SCALE 0.125f
#define SLD 264

#define BM 128
#define BN 128
#define BK 32
#define STAGES 3
#define LDA 36

// scratch: xr, q, k, v, go (5 x 16M) + 4 rounded weights
__device__ float g_scratch[5ull * MTOK * DIMC + 4ull * DIMC * DIMC];

// ---------------- helpers ----------------
__device__ __forceinline__ void cp_async16(void* smem, const void* gmem) {
    unsigned s = (unsigned)__cvta_generic_to_shared(smem);
    asm volatile("cp.async.cg.shared.global [%0], [%1], 16;\n" :: "r"(s), "l"(gmem));
}
__device__ __forceinline__ void cp_commit() {
    asm volatile("cp.async.commit_group;\n");
}
template<int N> __device__ __forceinline__ void cp_wait() {
    asm volatile("cp.async.wait_group %0;\n" :: "n"(N));
}
__device__ __forceinline__ float round_tf32(float x) {
    uint32_t u;
    asm("cvt.rna.tf32.f32 %0, %1;" : "=r"(u) : "f"(x));
    return __uint_as_float(u);
}

// ---------------------------------------------------------------------------
// tf32-RN rounding prepass
// ---------------------------------------------------------------------------
__global__ void round_tf32_kernel(const float4* __restrict__ src,
                                  float4* __restrict__ dst, int n4) {
    int i = blockIdx.x * blockDim.x + threadIdx.x;
    if (i >= n4) return;
    float4 v = src[i];
    v.x = round_tf32(v.x); v.y = round_tf32(v.y);
    v.z = round_tf32(v.z); v.w = round_tf32(v.w);
    dst[i] = v;
}

// ---------------------------------------------------------------------------
// C[M,1024] = A[M,1024] @ W[1024,1024]^T + bias.  A, W pre-rounded to tf32.
// 128x128 CTA tile, 4 warps, WARP TILE 64x64 (16 mma / 8 frag loads per kk),
// BK=32, 3-stage cp.async, one sync per K-tile, 2 CTAs/SM.
// ---------------------------------------------------------------------------
__global__ __launch_bounds__(128, 2) void gemm3_tf32(
    const float* __restrict__ A,
    const float* __restrict__ W0, const float* __restrict__ b0, float* __restrict__ C0,
    const float* __restrict__ W1, const float* __restrict__ b1, float* __restrict__ C1,
    const float* __restrict__ W2, const float* __restrict__ b2, float* __restrict__ C2,
    int roundOut)
{
    extern __shared__ float sm[];
    const float* Bw; const float* bias; float* C;
    if (blockIdx.z == 0)      { Bw = W0; bias = b0; C = C0; }
    else if (blockIdx.z == 1) { Bw = W1; bias = b1; C = C1; }
    else                      { Bw = W2; bias = b2; C = C2; }

    const int K = DIMC, N = DIMC;
    const int tid  = threadIdx.x;
    const int warp = tid >> 5;       // 0..3
    const int lane = tid & 31;
    const int wm = warp & 1;         // 2 warps along M (64 rows)
    const int wn = warp >> 1;        // 2 warps along N (64 cols)
    const int rowBase = blockIdx.y * BM;
    const int colBase = blockIdx.x * BN;

    const int stageF = BM * LDA;
    auto As = [&](int s) { return sm + (size_t)s * 2 * stageF; };
    auto Bs = [&](int s) { return sm + (size_t)s * 2 * stageF + stageF; };

    const int lr = tid >> 3;          // 0..15
    const int lc = (tid & 7) * 4;     // 0..28

    auto loadStage = [&](int s, int kt) {
        float* as = As(s); float* bs = Bs(s);
        int k0 = kt * BK;
        #pragma unroll
        for (int j = 0; j < 8; j++) {
            int r = lr + j * 16;
            cp_async16(&as[r * LDA + lc], &A [(size_t)(rowBase + r) * K + k0 + lc]);
            cp_async16(&bs[r * LDA + lc], &Bw[(size_t)(colBase + r) * K + k0 + lc]);
        }
        cp_commit();
    };

    wmma::fragment<wmma::accumulator,16,16,8,float> acc[4][4];
    #pragma unroll
    for (int i = 0; i < 4; i++)
        #pragma unroll
        for (int j = 0; j < 4; j++)
            wmma::fill_fragment(acc[i][j], 0.0f);

    const int NT = K / BK;            // 32
    loadStage(0, 0);
    loadStage(1, 1);

    for (int kt = 0; kt < NT; kt++) {
        if (kt + 1 < NT) cp_wait<1>();
        else             cp_wait<0>();
        __syncthreads();
        if (kt + 2 < NT) loadStage((kt + 2) % STAGES, kt + 2);

        const float* as = As(kt % STAGES);
        const float* bs = Bs(kt % STAGES);
        #pragma unroll
        for (int kk = 0; kk < BK; kk += 8) {
            wmma::fragment<wmma::matrix_a,16,16,8,wmma::precision::tf32,wmma::row_major> af[4];
            wmma::fragment<wmma::matrix_b,16,16,8,wmma::precision::tf32,wmma::col_major> bf[4];
            #pragma unroll
            for (int i = 0; i < 4; i++)
                wmma::load_matrix_sync(af[i], as + (wm*64 + i*16) * LDA + kk, LDA);
            #pragma unroll
            for (int j = 0; j < 4; j++)
                wmma::load_matrix_sync(bf[j], bs + (wn*64 + j*16) * LDA + kk, LDA);
            #pragma unroll
            for (int i = 0; i < 4; i++)
                #pragma unroll
                for (int j = 0; j < 4; j++)
                    wmma::mma_sync(acc[i][j], af[i], bf[j], acc[i][j]);
        }
    }
    __syncthreads();

    // epilogue: stage 16x16 tiles through smem, add bias, vector store
    float* wstg = sm + warp * 352;
    #pragma unroll
    for (int i = 0; i < 4; i++) {
        #pragma unroll
        for (int j = 0; j < 4; j++) {
            wmma::store_matrix_sync(wstg, acc[i][j], 20, wmma::mem_row_major);
            __syncwarp();
            int r0 = rowBase + wm*64 + i*16;
            int c0 = colBase + wn*64 + j*16;
            int r  = lane >> 1;
            int cc = (lane & 1) * 8;
            float o[8];
            #pragma unroll
            for (int t = 0; t < 8; t++)
                o[t] = wstg[r*20 + cc + t] + __ldg(&bias[c0 + cc + t]);
            if (roundOut) {
                #pragma unroll
                for (int t = 0; t < 8; t++) o[t] = round_tf32(o[t]);
            }
            *(float4*)&C[(size_t)(r0 + r) * N + c0 + cc]     = *(float4*)&o[0];
            *(float4*)&C[(size_t)(r0 + r) * N + c0 + cc + 4] = *(float4*)&o[4];
            __syncwarp();
        }
    }
}

// ---------------------------------------------------------------------------
// Block-local attention. One CTA per window, 512 threads. q,k,v pre-rounded
// tf32. P rounded in softmax; O rounded in epilogue (feeds tf32 Wo GEMM).
// ---------------------------------------------------------------------------
__global__ __launch_bounds__(512) void attn_kernel(
    const float* __restrict__ q, const float* __restrict__ k,
    const float* __restrict__ v, float* __restrict__ o,
    float* __restrict__ attnp)
{
    extern __shared__ float sm[];
    float* Ks = sm;
    float* Vs = Ks + 256*64;
    float* Qs = Vs + 256*64;
    float* Ss = Qs + 64*64;

    const int tid  = threadIdx.x;
    const int warp = tid >> 5;
    const int wm = warp >> 2;
    const int wn = warp & 3;

    const int bhw = blockIdx.x;
    const int w = bhw & 15;
    const int h = (bhw >> 4) & 15;
    const int b = bhw >> 8;

    const size_t tokBase = (size_t)b * SEQ + (size_t)w * BLKT;
    const int    colBase = h * HDIM;

    const float* Kg = k + tokBase * DIMC + colBase;
    const float* Vg = v + tokBase * DIMC + colBase;
    const float* Qg = q + tokBase * DIMC + colBase;

    #pragma unroll
    for (int j = 0; j < 8; j++) {
        int i = tid + j * 512;
        int r = i >> 4, c = (i & 15) * 4;
        cp_async16(&Ks[r*64 + c], Kg + (size_t)r * DIMC + c);
        cp_async16(&Vs[r*64 + c], Vg + (size_t)r * DIMC + c);
    }
    #pragma unroll
    for (int j = 0; j < 2; j++) {
        int i = tid + j * 512;
        int r = i >> 4, c = (i & 15) * 4;
        cp_async16(&Qs[r*64 + c], Qg + (size_t)r * DIMC + c);
    }
    cp_commit();
    cp_wait<0>();
    __syncthreads();

    for (int qc = 0; qc < 4; qc++) {
        // ---- S = Q @ K^T ----
        {
            wmma::fragment<wmma::accumulator,16,16,8,float> sacc[4];
            #pragma unroll
            for (int j = 0; j < 4; j++) wmma::fill_fragment(sacc[j], 0.0f);
            #pragma unroll
            for (int d0 = 0; d0 < HDIM; d0 += 8) {
                wmma::fragment<wmma::matrix_a,16,16,8,wmma::precision::tf32,wmma::row_major> af;
                wmma::load_matrix_sync(af, Qs + (wm*16)*HDIM + d0, HDIM);
                #pragma unroll
                for (int j = 0; j < 4; j++) {
                    wmma::fragment<wmma::matrix_b,16,16,8,wmma::precision::tf32,wmma::col_major> bf;
                    wmma::load_matrix_sync(bf, Ks + (size_t)(wn*64 + j*16)*HDIM + d0, HDIM);
                    wmma::mma_sync(sacc[j], af, bf, sacc[j]);
                }
            }
            #pragma unroll
            for (int j = 0; j < 4; j++)
                wmma::store_matrix_sync(Ss + (wm*16)*SLD + wn*64 + j*16, sacc[j],
                                        SLD, wmma::mem_row_major);
        }
        __syncthreads();

        if (qc < 3) {
            const float* Qn = Qg + (size_t)(qc + 1) * QCH * DIMC;
            #pragma unroll
            for (int j = 0; j < 2; j++) {
                int i = tid + j * 512;
                int r = i >> 4, c = (i & 15) * 4;
                cp_async16(&Qs[r*64 + c], Qn + (size_t)r * DIMC + c);
            }
            cp_commit();
        }

        // ---- softmax ----
        {
            const int row  = tid >> 3;
            const int part = tid & 7;
            float* srow = Ss + row * SLD;
            float mx = -1e30f;
            #pragma unroll
            for (int j = 0; j < 32; j++) mx = fmaxf(mx, srow[j*8 + part]);
            mx = fmaxf(mx, __shfl_xor_sync(0xffffffffu, mx, 1));
            mx = fmaxf(mx, __shfl_xor_sync(0xffffffffu, mx, 2));
            mx = fmaxf(mx, __shfl_xor_sync(0xffffffffu, mx, 4));
            float sum = 0.0f;
            #pragma unroll
            for (int j = 0; j < 32; j++) {
                float e = __expf((srow[j*8 + part] - mx) * ATTN_SCALE);
                srow[j*8 + part] = e;
                sum += e;
            }
            sum += __shfl_xor_sync(0xffffffffu, sum, 1);
            sum += __shfl_xor_sync(0xffffffffu, sum, 2);
            sum += __shfl_xor_sync(0xffffffffu, sum, 4);
            const float inv = 1.0f / sum;
            if (attnp) {
                float* arow = attnp + ((((size_t)b*NHEAD + h)*NWIN + w)*BLKT
                                       + qc*QCH + row) * BLKT;
                #pragma unroll
                for (int j = 0; j < 32; j++) {
                    float p = srow[j*8 + part] * inv;
                    __stcs(&arow[j*8 + part], p);
                    srow[j*8 + part] = round_tf32(p);
                }
            } else {
                #pragma unroll
                for (int j = 0; j < 32; j++)
                    srow[j*8 + part] = round_tf32(srow[j*8 + part] * inv);
            }
        }
        __syncthreads();

        // ---- O = P @ V (output rounded to tf32 for the Wo GEMM) ----
        {
            wmma::fragment<wmma::accumulator,16,16,8,float> oacc;
            wmma::fill_fragment(oacc, 0.0f);
            #pragma unroll 8
            for (int k0 = 0; k0 < BLKT; k0 += 8) {
                wmma::fragment<wmma::matrix_a,16,16,8,wmma::precision::tf32,wmma::row_major> af;
                wmma::load_matrix_sync(af, Ss + (wm*16)*SLD + k0, SLD);
                wmma::fragment<wmma::matrix_b,16,16,8,wmma::precision::tf32,wmma::row_major> bf;
                wmma::load_matrix_sync(bf, Vs + (size_t)k0*HDIM + wn*16, HDIM);
                wmma::mma_sync(oacc, af, bf, oacc);
            }
            #pragma unroll
            for (int e = 0; e < oacc.num_elements; e++)
                oacc.x[e] = round_tf32(oacc.x[e]);
            float* optr = o + (tokBase + (size_t)qc*QCH + wm*16) * DIMC
                            + colBase + wn*16;
            wmma::store_matrix_sync(optr, oacc, DIMC, wmma::mem_row_major);
        }

        if (qc < 3) cp_wait<0>();
        __syncthreads();
    }
}

// ---------------------------------------------------------------------------
extern "C" void kernel_launch(void* const* d_in, const int* in_sizes, int n_in,
                              void* d_out, int out_size)
{
    const float* x  = (const float*)d_in[0];
    const float* Wq = (const float*)d_in[1];
    const float* bq = (const float*)d_in[2];
    const float* Wk = (const float*)d_in[3];
    const float* bk = (const float*)d_in[4];
    const float* Wv = (const float*)d_in[5];
    const float* bv = (const float*)d_in[6];
    const float* Wo = (const float*)d_in[7];
    const float* bo = (const float*)d_in[8];

    float* out = (float*)d_out;
    const size_t out_elems = (size_t)MTOK * DIMC;
    float* attnp = ((size_t)out_size > out_elems) ? (out + out_elems) : nullptr;

    float* scratch = nullptr;
    cudaGetSymbolAddress((void**)&scratch, g_scratch);
    float* xr = scratch;
    float* gq = xr + out_elems;
    float* gk = gq + out_elems;
    float* gv = gk + out_elems;
    float* go = gv + out_elems;
    float* wr = go + out_elems;
    const size_t wsz = (size_t)DIMC * DIMC;
    float* wrq = wr;
    float* wrk = wr + wsz;
    float* wrv = wr + 2*wsz;
    float* wro = wr + 3*wsz;

    round_tf32_kernel<<<(int)(out_elems/4/256), 256>>>((const float4*)x,  (float4*)xr,  (int)(out_elems/4));
    round_tf32_kernel<<<(int)(wsz/4/256),       256>>>((const float4*)Wq, (float4*)wrq, (int)(wsz/4));
    round_tf32_kernel<<<(int)(wsz/4/256),       256>>>((const float4*)Wk, (float4*)wrk, (int)(wsz/4));
    round_tf32_kernel<<<(int)(wsz/4/256),       256>>>((const float4*)Wv, (float4*)wrv, (int)(wsz/4));
    round_tf32_kernel<<<(int)(wsz/4/256),       256>>>((const float4*)Wo, (float4*)wro, (int)(wsz/4));

    const size_t gemm_smem = (size_t)STAGES * 2 * BM * LDA * sizeof(float); // 110592
    cudaFuncSetAttribute(gemm3_tf32, cudaFuncAttributeMaxDynamicSharedMemorySize, (int)gemm_smem);

    dim3 gg(DIMC / BN, MTOK / BM, 3);
    gemm3_tf32<<<gg, 128, gemm_smem>>>(xr, wrq, bq, gq, wrk, bk, gk, wrv, bv, gv, 1);

    const size_t attn_smem = (size_t)(256*64*2 + 64*64 + 64*SLD) * sizeof(float);
    cudaFuncSetAttribute(attn_kernel, cudaFuncAttributeMaxDynamicSharedMemorySize, (int)attn_smem);
    attn_kernel<<<BATCH*NHEAD*NWIN, 512, attn_smem>>>(gq, gk, gv, go, attnp);

    dim3 go_grid(DIMC / BN, MTOK / BM, 1);
    gemm3_tf32<<<go_grid, 128, gemm_smem>>>(go, wro, bo, out, wro, bo, out, wro, bo, out, 0);
}